// round 4
// baseline (speedup 1.0000x reference)
#include <cuda_runtime.h>
#include <cstdint>
#include <cfloat>
#include <cmath>

typedef unsigned long long ULL;

// ---------------- scratch (no allocations allowed) ----------------
__device__ float g_ent[512];        // [B*C]
__device__ int   g_top[8 * 16];     // [B][P] selected channels in top-k rank order
__device__ int   g_unsel[8 * 48];   // [B][C-P] unselected channels, ascending

// ---------------- f32x2 packed helpers (sm_103a) ----------------
__device__ __forceinline__ ULL pack_dup(float a) {
    ULL r; asm("mov.b64 %0, {%1, %1};" : "=l"(r) : "f"(a)); return r;
}
__device__ __forceinline__ ULL pack2(float a, float b) {
    ULL r; asm("mov.b64 %0, {%1, %2};" : "=l"(r) : "f"(a), "f"(b)); return r;
}
__device__ __forceinline__ ULL fma2(ULL a, ULL b, ULL c) {
    ULL d; asm("fma.rn.f32x2 %0, %1, %2, %3;" : "=l"(d) : "l"(a), "l"(b), "l"(c)); return d;
}
__device__ __forceinline__ void unpack2(ULL v, float& lo, float& hi) {
    asm("mov.b64 {%0, %1}, %2;" : "=f"(lo), "=f"(hi) : "l"(v));
}

// ============================================================================
// Kernel 1: per-(b,c) min/max + 256-bin histogram + entropy.
// One block per channel (512 blocks), 256 threads, float4 loads, 2 passes.
// ============================================================================
__global__ __launch_bounds__(256) void k_hist_ent(const float* __restrict__ x) {
    const int bc  = blockIdx.x;
    const int tid = threadIdx.x;
    const float4* __restrict__ p =
        reinterpret_cast<const float4*>(x) + (size_t)bc * 16384;

    // ---- pass 1: min / max ----
    float mn = FLT_MAX, mx = -FLT_MAX;
    for (int i = tid; i < 16384; i += 256) {
        float4 v = __ldg(&p[i]);
        mn = fminf(mn, fminf(fminf(v.x, v.y), fminf(v.z, v.w)));
        mx = fmaxf(mx, fmaxf(fmaxf(v.x, v.y), fmaxf(v.z, v.w)));
    }
    #pragma unroll
    for (int o = 16; o; o >>= 1) {
        mn = fminf(mn, __shfl_xor_sync(0xffffffffu, mn, o));
        mx = fmaxf(mx, __shfl_xor_sync(0xffffffffu, mx, o));
    }
    __shared__ float s_mn[8], s_mx[8];
    __shared__ float s_bmn, s_bmx;
    __shared__ int   hist[256];
    const int w = tid >> 5, l = tid & 31;
    if (l == 0) { s_mn[w] = mn; s_mx[w] = mx; }
    __syncthreads();
    if (tid == 0) {
        float a = s_mn[0], b = s_mx[0];
        #pragma unroll
        for (int i = 1; i < 8; i++) { a = fminf(a, s_mn[i]); b = fmaxf(b, s_mx[i]); }
        s_bmn = a; s_bmx = b;
    }
    hist[tid] = 0;
    __syncthreads();

    // ---- pass 2: histogram (bin = int((x - min) / (max - min + eps) * 256)) ----
    const float bmn   = s_bmn;
    const float scale = 1.0f / (s_bmx - bmn + 1e-8f);
    for (int i = tid; i < 16384; i += 256) {
        float4 v = __ldg(&p[i]);
        {
            float f = (v.x - bmn) * scale; int b0 = (int)(f * 256.0f);
            b0 = b0 < 0 ? 0 : (b0 > 255 ? 255 : b0); atomicAdd(&hist[b0], 1);
        }
        {
            float f = (v.y - bmn) * scale; int b0 = (int)(f * 256.0f);
            b0 = b0 < 0 ? 0 : (b0 > 255 ? 255 : b0); atomicAdd(&hist[b0], 1);
        }
        {
            float f = (v.z - bmn) * scale; int b0 = (int)(f * 256.0f);
            b0 = b0 < 0 ? 0 : (b0 > 255 ? 255 : b0); atomicAdd(&hist[b0], 1);
        }
        {
            float f = (v.w - bmn) * scale; int b0 = (int)(f * 256.0f);
            b0 = b0 < 0 ? 0 : (b0 > 255 ? 255 : b0); atomicAdd(&hist[b0], 1);
        }
    }
    __syncthreads();

    // ---- entropy: h = cnt + eps; p = h / sum(h); ent = -sum(p*log(p + eps)) ----
    __shared__ float s_s[8];
    __shared__ float s_tot;
    float h = (float)hist[tid] + 1e-8f;
    float s = h;
    #pragma unroll
    for (int o = 16; o; o >>= 1) s += __shfl_xor_sync(0xffffffffu, s, o);
    if (l == 0) s_s[w] = s;
    __syncthreads();
    if (tid == 0) {
        float t = 0.f;
        #pragma unroll
        for (int i = 0; i < 8; i++) t += s_s[i];
        s_tot = t;
    }
    __syncthreads();
    float pr   = h / s_tot;
    float term = pr * logf(pr + 1e-8f);
    float e = term;
    #pragma unroll
    for (int o = 16; o; o >>= 1) e += __shfl_xor_sync(0xffffffffu, e, o);
    __syncthreads();           // everyone done with previous s_s use
    if (l == 0) s_s[w] = e;
    __syncthreads();
    if (tid == 0) {
        float t = 0.f;
        #pragma unroll
        for (int i = 0; i < 8; i++) t += s_s[i];
        g_ent[bc] = -t;
    }
}

// ============================================================================
// Kernel 2: top-16 per batch (descending value, ties -> lower index) +
//           unselected channel list in ascending order.
// ============================================================================
__global__ void k_topk() {
    const int b = blockIdx.x;
    if (threadIdx.x != 0) return;
    const float* e = g_ent + b * 64;
    ULL used = 0ull;
    for (int p = 0; p < 16; p++) {
        float best = -FLT_MAX; int bi = 0;
        for (int c = 0; c < 64; c++) {
            if (!((used >> c) & 1ull) && e[c] > best) { best = e[c]; bi = c; }
        }
        used |= 1ull << bi;
        g_top[b * 16 + p] = bi;
    }
    int j = 0;
    for (int c = 0; c < 64; c++)
        if (!((used >> c) & 1ull)) g_unsel[b * 48 + (j++)] = c;
}

// ============================================================================
// Kernel 3: copy the 48 unselected channels to out[b, 64+j] (float4).
// ============================================================================
__global__ __launch_bounds__(256) void k_copy(const float* __restrict__ x,
                                              float* __restrict__ out) {
    size_t i = (size_t)blockIdx.x * 256 + threadIdx.x;   // float4 index, 8*48*16384 total
    int b   = (int)(i / (48 * 16384));
    int rem = (int)(i - (size_t)b * (48 * 16384));
    int j   = rem >> 14;
    int pos = rem & 16383;
    int c   = g_unsel[b * 48 + j];
    const float4* src = reinterpret_cast<const float4*>(x)  + (((size_t)b * 64 + c)      << 14) + pos;
    float4*       dst = reinterpret_cast<float4*>(out)      + (((size_t)b * 112 + 64 + j) << 14) + pos;
    *dst = __ldg(src);
}

// ============================================================================
// Kernel 4: 3x3 conv, 16 selected in-channels -> 64 out-channels, pad=1.
// Tile: 16x64 output pixels, all 64 OC, one batch. f32x2 packed FMA over
// oc-pairs: weights in smem transposed [ic*9+tap][oc] so pair = LDS.64
// broadcast; per tap: 8 LDS.64(w) + 4 LDS.32(x) + 4 pack + 32 FFMA2.
// ============================================================================
__global__ __launch_bounds__(256) void k_conv(const float* __restrict__ x,
                                              const float* __restrict__ wgt,
                                              const float* __restrict__ bias,
                                              float* __restrict__ out) {
    extern __shared__ float smem[];
    float* s_x = smem;             // 16 * 18 * 66 = 19008 floats
    float* s_w = smem + 19008;     // 144 * 64    = 9216 floats  [ic*9+tap][oc]
    float* s_b = s_w + 9216;       // 64
    __shared__ int s_ch[16];

    const int tid = threadIdx.x;
    const int b   = blockIdx.z;
    const int by  = blockIdx.y * 16;
    const int bx  = blockIdx.x * 64;

    if (tid < 16) s_ch[tid] = g_top[b * 16 + tid];
    if (tid < 64) s_b[tid]  = __ldg(&bias[tid]);
    for (int i = tid; i < 9216; i += 256) {
        int oc = i & 63;
        int t  = i >> 6;                      // ic*9 + tap
        s_w[i] = __ldg(&wgt[oc * 144 + t]);
    }
    __syncthreads();                          // s_ch ready for x gather

    // halo-padded input tile: rows [by-1, by+16], cols [bx-1, bx+64]
    for (int i = tid; i < 19008; i += 256) {
        int ic = i / 1188;                    // 18*66
        int r  = (i - ic * 1188) / 66;
        int cx = i - ic * 1188 - r * 66;
        int gy = by - 1 + r, gx = bx - 1 + cx;
        float v = 0.f;
        if ((unsigned)gy < 256u && (unsigned)gx < 256u)
            v = __ldg(&x[(((size_t)(b * 64 + s_ch[ic])) << 16) + (gy << 8) + gx]);
        s_x[i] = v;
    }
    __syncthreads();

    const int col  = tid & 63;
    const int row0 = tid >> 6;                // pixels at rows row0 + 4p

    for (int ocg = 0; ocg < 4; ocg++) {
        ULL acc[8][4];
        #pragma unroll
        for (int o = 0; o < 8; o++) {
            ULL bb = pack2(s_b[ocg * 16 + 2 * o], s_b[ocg * 16 + 2 * o + 1]);
            #pragma unroll
            for (int p = 0; p < 4; p++) acc[o][p] = bb;
        }
        #pragma unroll 1
        for (int ic = 0; ic < 16; ic++) {
            const float* xc = s_x + ic * 1188 + row0 * 66 + col;
            const float* wc = s_w + ic * 9 * 64 + ocg * 16;
            #pragma unroll
            for (int tap = 0; tap < 9; tap++) {
                const int ky = tap / 3, kx = tap % 3;
                ULL w2[8];
                #pragma unroll
                for (int o = 0; o < 8; o++)
                    w2[o] = *reinterpret_cast<const ULL*>(wc + tap * 64 + 2 * o);
                #pragma unroll
                for (int p = 0; p < 4; p++) {
                    float xv = xc[(4 * p + ky) * 66 + kx];
                    ULL xx = pack_dup(xv);
                    #pragma unroll
                    for (int o = 0; o < 8; o++)
                        acc[o][p] = fma2(w2[o], xx, acc[o][p]);
                }
            }
        }
        #pragma unroll
        for (int p = 0; p < 4; p++) {
            int gy = by + row0 + 4 * p;
            float* ob = out + (((size_t)(b * 112 + ocg * 16)) << 16) + (gy << 8) + bx + col;
            #pragma unroll
            for (int o = 0; o < 8; o++) {
                float lo, hi;
                unpack2(acc[o][p], lo, hi);
                ob[((size_t)(2 * o))     << 16] = lo;
                ob[((size_t)(2 * o + 1)) << 16] = hi;
            }
        }
    }
}

// ============================================================================
// launcher
// ============================================================================
extern "C" void kernel_launch(void* const* d_in, const int* in_sizes, int n_in,
                              void* d_out, int out_size) {
    const float* x    = (const float*)d_in[0];   // [8,64,256,256]
    const float* wgt  = (const float*)d_in[1];   // [64,16,3,3]
    const float* bias = (const float*)d_in[2];   // [64]
    float* out = (float*)d_out;                  // [8,112,256,256]

    const int conv_smem = (19008 + 9216 + 64) * 4;   // 113152 bytes
    cudaFuncSetAttribute(k_conv, cudaFuncAttributeMaxDynamicSharedMemorySize, conv_smem);

    k_hist_ent<<<512, 256>>>(x);
    k_topk<<<8, 32>>>();
    k_copy<<<24576, 256>>>(x, out);
    k_conv<<<dim3(4, 16, 8), 256, conv_smem>>>(x, wgt, bias, out);
}

// round 5
// speedup vs baseline: 1.0013x; 1.0013x over previous
#include <cuda_runtime.h>
#include <cstdint>
#include <cfloat>
#include <cmath>

typedef unsigned long long ULL;

// ---------------- scratch (no allocations allowed) ----------------
__device__ float g_ent[512];        // [B*C]
__device__ int   g_top[8 * 16];     // [B][P] selected channels in top-k rank order
__device__ int   g_unsel[8 * 48];   // [B][C-P] unselected channels, ascending

// ---------------- f32x2 packed helpers (sm_103a) ----------------
__device__ __forceinline__ ULL pack_dup(float a) {
    ULL r; asm("mov.b64 %0, {%1, %1};" : "=l"(r) : "f"(a)); return r;
}
__device__ __forceinline__ ULL pack2(float a, float b) {
    ULL r; asm("mov.b64 %0, {%1, %2};" : "=l"(r) : "f"(a), "f"(b)); return r;
}
__device__ __forceinline__ ULL fma2(ULL a, ULL b, ULL c) {
    ULL d; asm("fma.rn.f32x2 %0, %1, %2, %3;" : "=l"(d) : "l"(a), "l"(b), "l"(c)); return d;
}
__device__ __forceinline__ void unpack2(ULL v, float& lo, float& hi) {
    asm("mov.b64 {%0, %1}, %2;" : "=f"(lo), "=f"(hi) : "l"(v));
}

// ============================================================================
// Kernel 1: per-(b,c) min/max + 256-bin histogram + entropy.
// One block per channel (512 blocks), 256 threads, float4 loads, 2 passes.
// ============================================================================
__global__ __launch_bounds__(256) void k_hist_ent(const float* __restrict__ x) {
    const int bc  = blockIdx.x;
    const int tid = threadIdx.x;
    const float4* __restrict__ p =
        reinterpret_cast<const float4*>(x) + (size_t)bc * 16384;

    // ---- pass 1: min / max ----
    float mn = FLT_MAX, mx = -FLT_MAX;
    for (int i = tid; i < 16384; i += 256) {
        float4 v = __ldg(&p[i]);
        mn = fminf(mn, fminf(fminf(v.x, v.y), fminf(v.z, v.w)));
        mx = fmaxf(mx, fmaxf(fmaxf(v.x, v.y), fmaxf(v.z, v.w)));
    }
    #pragma unroll
    for (int o = 16; o; o >>= 1) {
        mn = fminf(mn, __shfl_xor_sync(0xffffffffu, mn, o));
        mx = fmaxf(mx, __shfl_xor_sync(0xffffffffu, mx, o));
    }
    __shared__ float s_mn[8], s_mx[8];
    __shared__ float s_bmn, s_bmx;
    __shared__ int   hist[256];
    const int w = tid >> 5, l = tid & 31;
    if (l == 0) { s_mn[w] = mn; s_mx[w] = mx; }
    __syncthreads();
    if (tid == 0) {
        float a = s_mn[0], b = s_mx[0];
        #pragma unroll
        for (int i = 1; i < 8; i++) { a = fminf(a, s_mn[i]); b = fmaxf(b, s_mx[i]); }
        s_bmn = a; s_bmx = b;
    }
    hist[tid] = 0;
    __syncthreads();

    // ---- pass 2: histogram (bin = int((x - min) / (max - min + eps) * 256)) ----
    const float bmn   = s_bmn;
    const float scale = 1.0f / (s_bmx - bmn + 1e-8f);
    for (int i = tid; i < 16384; i += 256) {
        float4 v = __ldg(&p[i]);
        {
            float f = (v.x - bmn) * scale; int b0 = (int)(f * 256.0f);
            b0 = b0 < 0 ? 0 : (b0 > 255 ? 255 : b0); atomicAdd(&hist[b0], 1);
        }
        {
            float f = (v.y - bmn) * scale; int b0 = (int)(f * 256.0f);
            b0 = b0 < 0 ? 0 : (b0 > 255 ? 255 : b0); atomicAdd(&hist[b0], 1);
        }
        {
            float f = (v.z - bmn) * scale; int b0 = (int)(f * 256.0f);
            b0 = b0 < 0 ? 0 : (b0 > 255 ? 255 : b0); atomicAdd(&hist[b0], 1);
        }
        {
            float f = (v.w - bmn) * scale; int b0 = (int)(f * 256.0f);
            b0 = b0 < 0 ? 0 : (b0 > 255 ? 255 : b0); atomicAdd(&hist[b0], 1);
        }
    }
    __syncthreads();

    // ---- entropy: h = cnt + eps; p = h / sum(h); ent = -sum(p*log(p + eps)) ----
    __shared__ float s_s[8];
    __shared__ float s_tot;
    float h = (float)hist[tid] + 1e-8f;
    float s = h;
    #pragma unroll
    for (int o = 16; o; o >>= 1) s += __shfl_xor_sync(0xffffffffu, s, o);
    if (l == 0) s_s[w] = s;
    __syncthreads();
    if (tid == 0) {
        float t = 0.f;
        #pragma unroll
        for (int i = 0; i < 8; i++) t += s_s[i];
        s_tot = t;
    }
    __syncthreads();
    float pr   = h / s_tot;
    float term = pr * logf(pr + 1e-8f);
    float e = term;
    #pragma unroll
    for (int o = 16; o; o >>= 1) e += __shfl_xor_sync(0xffffffffu, e, o);
    __syncthreads();           // everyone done with previous s_s use
    if (l == 0) s_s[w] = e;
    __syncthreads();
    if (tid == 0) {
        float t = 0.f;
        #pragma unroll
        for (int i = 0; i < 8; i++) t += s_s[i];
        g_ent[bc] = -t;
    }
}

// ============================================================================
// Kernel 2: top-16 per batch (descending value, ties -> lower index) +
//           unselected channel list in ascending order.
// ============================================================================
__global__ void k_topk() {
    const int b = blockIdx.x;
    if (threadIdx.x != 0) return;
    const float* e = g_ent + b * 64;
    ULL used = 0ull;
    for (int p = 0; p < 16; p++) {
        float best = -FLT_MAX; int bi = 0;
        for (int c = 0; c < 64; c++) {
            if (!((used >> c) & 1ull) && e[c] > best) { best = e[c]; bi = c; }
        }
        used |= 1ull << bi;
        g_top[b * 16 + p] = bi;
    }
    int j = 0;
    for (int c = 0; c < 64; c++)
        if (!((used >> c) & 1ull)) g_unsel[b * 48 + (j++)] = c;
}

// ============================================================================
// Kernel 3: copy the 48 unselected channels to out[b, 64+j] (float4).
// ============================================================================
__global__ __launch_bounds__(256) void k_copy(const float* __restrict__ x,
                                              float* __restrict__ out) {
    size_t i = (size_t)blockIdx.x * 256 + threadIdx.x;   // float4 index, 8*48*16384 total
    int b   = (int)(i / (48 * 16384));
    int rem = (int)(i - (size_t)b * (48 * 16384));
    int j   = rem >> 14;
    int pos = rem & 16383;
    int c   = g_unsel[b * 48 + j];
    const float4* src = reinterpret_cast<const float4*>(x)  + (((size_t)b * 64 + c)      << 14) + pos;
    float4*       dst = reinterpret_cast<float4*>(out)      + (((size_t)b * 112 + 64 + j) << 14) + pos;
    *dst = __ldg(src);
}

// ============================================================================
// Kernel 4: 3x3 conv, 16 selected in-channels -> 64 out-channels, pad=1.
// Tile: 16x64 output pixels, all 64 OC, one batch. f32x2 packed FMA over
// oc-pairs: weights in smem transposed [ic*9+tap][oc] so pair = LDS.64
// broadcast; per tap: 8 LDS.64(w) + 4 LDS.32(x) + 4 pack + 32 FFMA2.
// ============================================================================
__global__ __launch_bounds__(256) void k_conv(const float* __restrict__ x,
                                              const float* __restrict__ wgt,
                                              const float* __restrict__ bias,
                                              float* __restrict__ out) {
    extern __shared__ float smem[];
    float* s_x = smem;             // 16 * 18 * 66 = 19008 floats
    float* s_w = smem + 19008;     // 144 * 64    = 9216 floats  [ic*9+tap][oc]
    float* s_b = s_w + 9216;       // 64
    __shared__ int s_ch[16];

    const int tid = threadIdx.x;
    const int b   = blockIdx.z;
    const int by  = blockIdx.y * 16;
    const int bx  = blockIdx.x * 64;

    if (tid < 16) s_ch[tid] = g_top[b * 16 + tid];
    if (tid < 64) s_b[tid]  = __ldg(&bias[tid]);
    for (int i = tid; i < 9216; i += 256) {
        int oc = i & 63;
        int t  = i >> 6;                      // ic*9 + tap
        s_w[i] = __ldg(&wgt[oc * 144 + t]);
    }
    __syncthreads();                          // s_ch ready for x gather

    // halo-padded input tile: rows [by-1, by+16], cols [bx-1, bx+64]
    for (int i = tid; i < 19008; i += 256) {
        int ic = i / 1188;                    // 18*66
        int r  = (i - ic * 1188) / 66;
        int cx = i - ic * 1188 - r * 66;
        int gy = by - 1 + r, gx = bx - 1 + cx;
        float v = 0.f;
        if ((unsigned)gy < 256u && (unsigned)gx < 256u)
            v = __ldg(&x[(((size_t)(b * 64 + s_ch[ic])) << 16) + (gy << 8) + gx]);
        s_x[i] = v;
    }
    __syncthreads();

    const int col  = tid & 63;
    const int row0 = tid >> 6;                // pixels at rows row0 + 4p

    for (int ocg = 0; ocg < 4; ocg++) {
        ULL acc[8][4];
        #pragma unroll
        for (int o = 0; o < 8; o++) {
            ULL bb = pack2(s_b[ocg * 16 + 2 * o], s_b[ocg * 16 + 2 * o + 1]);
            #pragma unroll
            for (int p = 0; p < 4; p++) acc[o][p] = bb;
        }
        #pragma unroll 1
        for (int ic = 0; ic < 16; ic++) {
            const float* xc = s_x + ic * 1188 + row0 * 66 + col;
            const float* wc = s_w + ic * 9 * 64 + ocg * 16;
            #pragma unroll
            for (int tap = 0; tap < 9; tap++) {
                const int ky = tap / 3, kx = tap % 3;
                ULL w2[8];
                #pragma unroll
                for (int o = 0; o < 8; o++)
                    w2[o] = *reinterpret_cast<const ULL*>(wc + tap * 64 + 2 * o);
                #pragma unroll
                for (int p = 0; p < 4; p++) {
                    float xv = xc[(4 * p + ky) * 66 + kx];
                    ULL xx = pack_dup(xv);
                    #pragma unroll
                    for (int o = 0; o < 8; o++)
                        acc[o][p] = fma2(w2[o], xx, acc[o][p]);
                }
            }
        }
        #pragma unroll
        for (int p = 0; p < 4; p++) {
            int gy = by + row0 + 4 * p;
            float* ob = out + (((size_t)(b * 112 + ocg * 16)) << 16) + (gy << 8) + bx + col;
            #pragma unroll
            for (int o = 0; o < 8; o++) {
                float lo, hi;
                unpack2(acc[o][p], lo, hi);
                ob[((size_t)(2 * o))     << 16] = lo;
                ob[((size_t)(2 * o + 1)) << 16] = hi;
            }
        }
    }
}

// ============================================================================
// launcher
// ============================================================================
extern "C" void kernel_launch(void* const* d_in, const int* in_sizes, int n_in,
                              void* d_out, int out_size) {
    const float* x    = (const float*)d_in[0];   // [8,64,256,256]
    const float* wgt  = (const float*)d_in[1];   // [64,16,3,3]
    const float* bias = (const float*)d_in[2];   // [64]
    float* out = (float*)d_out;                  // [8,112,256,256]

    const int conv_smem = (19008 + 9216 + 64) * 4;   // 113152 bytes
    cudaFuncSetAttribute(k_conv, cudaFuncAttributeMaxDynamicSharedMemorySize, conv_smem);

    k_hist_ent<<<512, 256>>>(x);
    k_topk<<<8, 32>>>();
    k_copy<<<24576, 256>>>(x, out);
    k_conv<<<dim3(4, 16, 8), 256, conv_smem>>>(x, wgt, bias, out);
}